// round 1
// baseline (speedup 1.0000x reference)
#include <cuda_runtime.h>
#include <math.h>

#define B_ 4
#define N_ 2048
#define C_ 1024
#define H_ 16
#define D_ 64
#define M_ (B_*N_)            // 8192 rows total
#define QKV_N (3*C_)          // 3072
#define ATT_SCALE 0.125f      // 64^-0.5

// Scratch (allocation-free rule: __device__ globals)
__device__ float g_q[B_*H_*N_*D_];     // [B,H,N,D]
__device__ float g_k[B_*H_*N_*D_];
__device__ float g_v[B_*H_*N_*D_];
__device__ float g_att[M_*C_];         // [B,N,C] attention output

// ---------------------------------------------------------------------------
// GEMM core: Y = A(M x K) * W(Nout x K)^T  (both K-contiguous), K = 1024.
// 128x128 block tile, BK=16, 256 threads, 8x8 register tile per thread.
// ---------------------------------------------------------------------------

__global__ __launch_bounds__(256) void qkv_gemm_kernel(
    const float* __restrict__ x, const float* __restrict__ w,
    const float* __restrict__ bias)
{
    __shared__ float As[16][132];
    __shared__ float Bs[16][132];
    const int K = C_;
    const int tid = threadIdx.x;
    const int m0 = blockIdx.y * 128;
    const int n0 = blockIdx.x * 128;
    const int ty = tid >> 4;
    const int tx = tid & 15;
    const int lrow = tid >> 2;          // 0..63
    const int lcol = (tid & 3) << 2;    // 0,4,8,12

    float acc[8][8];
#pragma unroll
    for (int i = 0; i < 8; i++)
#pragma unroll
        for (int j = 0; j < 8; j++) acc[i][j] = 0.f;

    for (int k0 = 0; k0 < K; k0 += 16) {
#pragma unroll
        for (int s = 0; s < 2; s++) {
            int r = lrow + s * 64;
            float4 av = *(const float4*)(x + (m0 + r) * K + k0 + lcol);
            As[lcol + 0][r] = av.x; As[lcol + 1][r] = av.y;
            As[lcol + 2][r] = av.z; As[lcol + 3][r] = av.w;
            float4 wv = *(const float4*)(w + (n0 + r) * K + k0 + lcol);
            Bs[lcol + 0][r] = wv.x; Bs[lcol + 1][r] = wv.y;
            Bs[lcol + 2][r] = wv.z; Bs[lcol + 3][r] = wv.w;
        }
        __syncthreads();
#pragma unroll
        for (int kk = 0; kk < 16; kk++) {
            float4 a0 = *(const float4*)&As[kk][ty * 8];
            float4 a1 = *(const float4*)&As[kk][ty * 8 + 4];
            float4 b0 = *(const float4*)&Bs[kk][tx * 8];
            float4 b1 = *(const float4*)&Bs[kk][tx * 8 + 4];
            float ar[8] = {a0.x, a0.y, a0.z, a0.w, a1.x, a1.y, a1.z, a1.w};
            float br[8] = {b0.x, b0.y, b0.z, b0.w, b1.x, b1.y, b1.z, b1.w};
#pragma unroll
            for (int i = 0; i < 8; i++)
#pragma unroll
                for (int j = 0; j < 8; j++)
                    acc[i][j] = fmaf(ar[i], br[j], acc[i][j]);
        }
        __syncthreads();
    }

    // Epilogue: bias + scatter to q/k/v in [B,H,N,D]
#pragma unroll
    for (int i = 0; i < 8; i++) {
        int m = m0 + ty * 8 + i;
        int bb = m >> 11;        // / N_
        int n  = m & (N_ - 1);
#pragma unroll
        for (int j = 0; j < 8; j++) {
            int o = n0 + tx * 8 + j;
            float val = acc[i][j] + bias[o];
            int which = o >> 10;           // 0=q 1=k 2=v
            int rem = o & 1023;
            int h = rem >> 6;
            int d = rem & 63;
            float* dst = (which == 0) ? g_q : (which == 1) ? g_k : g_v;
            dst[((bb * H_ + h) * N_ + n) * D_ + d] = val;
        }
    }
}

__global__ __launch_bounds__(256) void proj_gemm_kernel(
    const float* __restrict__ w, const float* __restrict__ bias,
    float* __restrict__ out)
{
    __shared__ float As[16][132];
    __shared__ float Bs[16][132];
    const int K = C_;
    const int tid = threadIdx.x;
    const int m0 = blockIdx.y * 128;
    const int n0 = blockIdx.x * 128;
    const int ty = tid >> 4;
    const int tx = tid & 15;
    const int lrow = tid >> 2;
    const int lcol = (tid & 3) << 2;

    float acc[8][8];
#pragma unroll
    for (int i = 0; i < 8; i++)
#pragma unroll
        for (int j = 0; j < 8; j++) acc[i][j] = 0.f;

    for (int k0 = 0; k0 < K; k0 += 16) {
#pragma unroll
        for (int s = 0; s < 2; s++) {
            int r = lrow + s * 64;
            float4 av = *(const float4*)(g_att + (m0 + r) * K + k0 + lcol);
            As[lcol + 0][r] = av.x; As[lcol + 1][r] = av.y;
            As[lcol + 2][r] = av.z; As[lcol + 3][r] = av.w;
            float4 wv = *(const float4*)(w + (n0 + r) * K + k0 + lcol);
            Bs[lcol + 0][r] = wv.x; Bs[lcol + 1][r] = wv.y;
            Bs[lcol + 2][r] = wv.z; Bs[lcol + 3][r] = wv.w;
        }
        __syncthreads();
#pragma unroll
        for (int kk = 0; kk < 16; kk++) {
            float4 a0 = *(const float4*)&As[kk][ty * 8];
            float4 a1 = *(const float4*)&As[kk][ty * 8 + 4];
            float4 b0 = *(const float4*)&Bs[kk][tx * 8];
            float4 b1 = *(const float4*)&Bs[kk][tx * 8 + 4];
            float ar[8] = {a0.x, a0.y, a0.z, a0.w, a1.x, a1.y, a1.z, a1.w};
            float br[8] = {b0.x, b0.y, b0.z, b0.w, b1.x, b1.y, b1.z, b1.w};
#pragma unroll
            for (int i = 0; i < 8; i++)
#pragma unroll
                for (int j = 0; j < 8; j++)
                    acc[i][j] = fmaf(ar[i], br[j], acc[i][j]);
        }
        __syncthreads();
    }

#pragma unroll
    for (int i = 0; i < 8; i++) {
        int m = m0 + ty * 8 + i;
#pragma unroll
        for (int j = 0; j < 8; j++) {
            int o = n0 + tx * 8 + j;
            out[m * C_ + o] = acc[i][j] + bias[o];
        }
    }
}

// ---------------------------------------------------------------------------
// Flash attention: one CTA per (b,h, 64-row Q tile). BR=64, BC=32, D=64.
// 256 threads as 16(ty, rows) x 16(tx). Thread S-tile 4x2, O-tile 4x4.
// ---------------------------------------------------------------------------
__global__ __launch_bounds__(256) void attn_kernel()
{
    __shared__ float Qs[64][64];   // [d][row], SCALE folded in
    __shared__ float Ks[64][32];   // [d][col]
    __shared__ float Vs[32][64];   // [col][d]
    __shared__ float Ps[64][32];   // [row][col]

    const int tid = threadIdx.x;
    const int tx = tid & 15;
    const int ty = tid >> 4;
    const int bh = blockIdx.y;          // b*H + h
    const int bb = bh >> 4;
    const int h  = bh & 15;
    const int r0 = blockIdx.x * 64;

    const float* qp = g_q + bh * (N_ * D_);
    const float* kp = g_k + bh * (N_ * D_);
    const float* vp = g_v + bh * (N_ * D_);

    // Load Q tile (transposed to [d][row]) with SCALE folded in
    for (int s = tid; s < 64 * 16; s += 256) {
        int r = s >> 4;
        int d4 = (s & 15) << 2;
        float4 qv = *(const float4*)(qp + (r0 + r) * D_ + d4);
        Qs[d4 + 0][r] = qv.x * ATT_SCALE;
        Qs[d4 + 1][r] = qv.y * ATT_SCALE;
        Qs[d4 + 2][r] = qv.z * ATT_SCALE;
        Qs[d4 + 3][r] = qv.w * ATT_SCALE;
    }

    float mloc[4], lloc[4], oacc[4][4];
#pragma unroll
    for (int i = 0; i < 4; i++) {
        mloc[i] = -1e30f;
        lloc[i] = 0.f;
#pragma unroll
        for (int j = 0; j < 4; j++) oacc[i][j] = 0.f;
    }
    __syncthreads();

    for (int c0 = 0; c0 < N_; c0 += 32) {
        __syncthreads();   // previous PV reads of Vs/Ps complete
        // Load K (transposed) and V (natural)
        for (int s = tid; s < 32 * 16; s += 256) {
            int c = s >> 4;
            int d4 = (s & 15) << 2;
            float4 kv = *(const float4*)(kp + (c0 + c) * D_ + d4);
            Ks[d4 + 0][c] = kv.x; Ks[d4 + 1][c] = kv.y;
            Ks[d4 + 2][c] = kv.z; Ks[d4 + 3][c] = kv.w;
            float4 vv = *(const float4*)(vp + (c0 + c) * D_ + d4);
            *(float4*)&Vs[c][d4] = vv;
        }
        __syncthreads();

        // S = (Q*scale) K^T  — thread tile: rows ty*4..+3, cols tx*2..+1
        float s_[4][2] = {{0.f, 0.f}, {0.f, 0.f}, {0.f, 0.f}, {0.f, 0.f}};
#pragma unroll 8
        for (int d = 0; d < 64; d++) {
            float4 rq = *(const float4*)&Qs[d][ty * 4];
            float2 rk = *(const float2*)&Ks[d][tx * 2];
            s_[0][0] = fmaf(rq.x, rk.x, s_[0][0]);
            s_[0][1] = fmaf(rq.x, rk.y, s_[0][1]);
            s_[1][0] = fmaf(rq.y, rk.x, s_[1][0]);
            s_[1][1] = fmaf(rq.y, rk.y, s_[1][1]);
            s_[2][0] = fmaf(rq.z, rk.x, s_[2][0]);
            s_[2][1] = fmaf(rq.z, rk.y, s_[2][1]);
            s_[3][0] = fmaf(rq.w, rk.x, s_[3][0]);
            s_[3][1] = fmaf(rq.w, rk.y, s_[3][1]);
        }

        // Online softmax update (rows owned by same ty across 16 tx lanes)
#pragma unroll
        for (int i = 0; i < 4; i++) {
            float t = fmaxf(s_[i][0], s_[i][1]);
            t = fmaxf(t, __shfl_xor_sync(0xffffffffu, t, 1, 16));
            t = fmaxf(t, __shfl_xor_sync(0xffffffffu, t, 2, 16));
            t = fmaxf(t, __shfl_xor_sync(0xffffffffu, t, 4, 16));
            t = fmaxf(t, __shfl_xor_sync(0xffffffffu, t, 8, 16));
            float mnew = fmaxf(mloc[i], t);
            float alpha = __expf(mloc[i] - mnew);
            mloc[i] = mnew;
            float p0 = __expf(s_[i][0] - mnew);
            float p1 = __expf(s_[i][1] - mnew);
            float rs = p0 + p1;
            rs += __shfl_xor_sync(0xffffffffu, rs, 1, 16);
            rs += __shfl_xor_sync(0xffffffffu, rs, 2, 16);
            rs += __shfl_xor_sync(0xffffffffu, rs, 4, 16);
            rs += __shfl_xor_sync(0xffffffffu, rs, 8, 16);
            lloc[i] = lloc[i] * alpha + rs;
            oacc[i][0] *= alpha; oacc[i][1] *= alpha;
            oacc[i][2] *= alpha; oacc[i][3] *= alpha;
            *(float2*)&Ps[ty * 4 + i][tx * 2] = make_float2(p0, p1);
        }
        __syncthreads();

        // O += P @ V — thread tile: rows ty*4..+3, d-cols tx*4..+3
#pragma unroll 4
        for (int c = 0; c < 32; c++) {
            float4 rv = *(const float4*)&Vs[c][tx * 4];
            float p0 = Ps[ty * 4 + 0][c];
            float p1 = Ps[ty * 4 + 1][c];
            float p2 = Ps[ty * 4 + 2][c];
            float p3 = Ps[ty * 4 + 3][c];
            oacc[0][0] = fmaf(p0, rv.x, oacc[0][0]);
            oacc[0][1] = fmaf(p0, rv.y, oacc[0][1]);
            oacc[0][2] = fmaf(p0, rv.z, oacc[0][2]);
            oacc[0][3] = fmaf(p0, rv.w, oacc[0][3]);
            oacc[1][0] = fmaf(p1, rv.x, oacc[1][0]);
            oacc[1][1] = fmaf(p1, rv.y, oacc[1][1]);
            oacc[1][2] = fmaf(p1, rv.z, oacc[1][2]);
            oacc[1][3] = fmaf(p1, rv.w, oacc[1][3]);
            oacc[2][0] = fmaf(p2, rv.x, oacc[2][0]);
            oacc[2][1] = fmaf(p2, rv.y, oacc[2][1]);
            oacc[2][2] = fmaf(p2, rv.z, oacc[2][2]);
            oacc[2][3] = fmaf(p2, rv.w, oacc[2][3]);
            oacc[3][0] = fmaf(p3, rv.x, oacc[3][0]);
            oacc[3][1] = fmaf(p3, rv.y, oacc[3][1]);
            oacc[3][2] = fmaf(p3, rv.z, oacc[3][2]);
            oacc[3][3] = fmaf(p3, rv.w, oacc[3][3]);
        }
    }

    // Finalize: divide by l, write to g_att in [B,N,C] layout
#pragma unroll
    for (int i = 0; i < 4; i++) {
        float inv = 1.f / lloc[i];
        int n = r0 + ty * 4 + i;
        float4 ov = make_float4(oacc[i][0] * inv, oacc[i][1] * inv,
                                oacc[i][2] * inv, oacc[i][3] * inv);
        *(float4*)&g_att[(bb * N_ + n) * C_ + h * D_ + tx * 4] = ov;
    }
}

// ---------------------------------------------------------------------------

extern "C" void kernel_launch(void* const* d_in, const int* in_sizes, int n_in,
                              void* d_out, int out_size)
{
    const float* x      = (const float*)d_in[0];
    const float* w_qkv  = (const float*)d_in[1];
    const float* b_qkv  = (const float*)d_in[2];
    const float* w_proj = (const float*)d_in[3];
    const float* b_proj = (const float*)d_in[4];
    float* out = (float*)d_out;

    qkv_gemm_kernel<<<dim3(QKV_N / 128, M_ / 128), 256>>>(x, w_qkv, b_qkv);
    attn_kernel<<<dim3(N_ / 64, B_ * H_), 256>>>();
    proj_gemm_kernel<<<dim3(C_ / 128, M_ / 128), 256>>>(w_proj, b_proj, out);
}

// round 3
// speedup vs baseline: 6.4149x; 6.4149x over previous
#include <cuda_runtime.h>
#include <cuda_fp16.h>
#include <cstdint>

#define B_ 4
#define N_ 2048
#define C_ 1024
#define H_ 16
#define D_ 64
#define M_ (B_*N_)            // 8192
#define QKV_N (3*C_)          // 3072

// ---------------- scratch (__device__ globals; no allocation) ---------------
__device__ __half g_xh[M_*C_];          // x fp16 [M,C]
__device__ __half g_wqh[QKV_N*C_];      // w_qkv fp16 [3C,C]
__device__ __half g_wph[C_*C_];         // w_proj fp16 [C,C]
__device__ __half g_qh[B_*H_*N_*D_];    // q fp16 [B,H,N,D] (scale folded)
__device__ __half g_kh[B_*H_*N_*D_];
__device__ __half g_vh[B_*H_*N_*D_];
__device__ __half g_ah[M_*C_];          // attn out fp16 [B,N,C]

// ---------------- helpers ---------------------------------------------------
__device__ __forceinline__ uint32_t su32(const void* p) {
    uint32_t a;
    asm("{ .reg .u64 t; cvta.to.shared.u64 t, %1; cvt.u32.u64 %0, t; }"
        : "=r"(a) : "l"(p));
    return a;
}
__device__ __forceinline__ void ldsm4(uint32_t* r, uint32_t a) {
    asm volatile("ldmatrix.sync.aligned.m8n8.x4.shared.b16 {%0,%1,%2,%3}, [%4];"
        : "=r"(r[0]), "=r"(r[1]), "=r"(r[2]), "=r"(r[3]) : "r"(a));
}
__device__ __forceinline__ void ldsm4t(uint32_t* r, uint32_t a) {
    asm volatile("ldmatrix.sync.aligned.m8n8.x4.trans.shared.b16 {%0,%1,%2,%3}, [%4];"
        : "=r"(r[0]), "=r"(r[1]), "=r"(r[2]), "=r"(r[3]) : "r"(a));
}
__device__ __forceinline__ void mma16816(float* d, const uint32_t* a,
                                         uint32_t b0, uint32_t b1) {
    asm volatile(
        "mma.sync.aligned.m16n8k16.row.col.f32.f16.f16.f32 "
        "{%0,%1,%2,%3}, {%4,%5,%6,%7}, {%8,%9}, {%0,%1,%2,%3};"
        : "+f"(d[0]), "+f"(d[1]), "+f"(d[2]), "+f"(d[3])
        : "r"(a[0]), "r"(a[1]), "r"(a[2]), "r"(a[3]), "r"(b0), "r"(b1));
}
// pack two f32 into f16x2; first operand -> HIGH half
__device__ __forceinline__ uint32_t pk2(float hi, float lo) {
    uint32_t r;
    asm("cvt.rn.f16x2.f32 %0, %1, %2;" : "=r"(r) : "f"(hi), "f"(lo));
    return r;
}

// ---------------- f32 -> f16 converts ---------------------------------------
template<int WHICH>
__global__ void cvt_kernel(const float* __restrict__ s, int n) {
    int i = (blockIdx.x * 256 + threadIdx.x) * 4;
    if (i < n) {
        __half* d = (WHICH == 0) ? g_xh : (WHICH == 1) ? g_wqh : g_wph;
        float4 v = *(const float4*)(s + i);
        __half2 lo = __floats2half2_rn(v.x, v.y);
        __half2 hi = __floats2half2_rn(v.z, v.w);
        *(__half2*)&d[i]     = lo;
        *(__half2*)&d[i + 2] = hi;
    }
}

// ---------------- HMMA GEMM: Y(M x Nout) = A(M x 1024) * W(Nout x 1024)^T ---
// Block 128x256 (8 warps, 2m x 4n), warp 64x64, BK=32.
// MODE 0: qkv -> scatter q/k/v fp16 (scale folded into q). MODE 1: proj -> f32 out.
template<int MODE>
__global__ __launch_bounds__(256) void gemm_h(const float* __restrict__ bias,
                                              float* __restrict__ out)
{
    __shared__ __half As[128][40];
    __shared__ __half Bs[256][40];
    const int tid = threadIdx.x, lane = tid & 31, wid = tid >> 5;
    const int wm = wid & 1, wn = wid >> 1;
    const int m0 = blockIdx.y * 128, n0 = blockIdx.x * 256;
    const __half* A  = (MODE == 0) ? g_xh  : g_ah;
    const __half* Bm = (MODE == 0) ? g_wqh : g_wph;

    float acc[4][8][4];
#pragma unroll
    for (int mt = 0; mt < 4; mt++)
#pragma unroll
        for (int nt = 0; nt < 8; nt++)
#pragma unroll
            for (int r = 0; r < 4; r++) acc[mt][nt][r] = 0.f;

    for (int kb = 0; kb < C_; kb += 32) {
        __syncthreads();
#pragma unroll
        for (int u = tid; u < 512; u += 256) {
            int r = u >> 2, sg = u & 3;
            *(uint4*)&As[r][sg * 8] = *(const uint4*)(A + (m0 + r) * C_ + kb + sg * 8);
        }
#pragma unroll
        for (int u = tid; u < 1024; u += 256) {
            int r = u >> 2, sg = u & 3;
            *(uint4*)&Bs[r][sg * 8] = *(const uint4*)(Bm + (n0 + r) * C_ + kb + sg * 8);
        }
        __syncthreads();
#pragma unroll
        for (int kk = 0; kk < 2; kk++) {
            uint32_t af[4][4], bf[4][4];
#pragma unroll
            for (int mt = 0; mt < 4; mt++)
                ldsm4(af[mt], su32(&As[wm * 64 + mt * 16 + (lane & 15)]
                                     [kk * 16 + (lane >> 4) * 8]));
#pragma unroll
            for (int p4 = 0; p4 < 4; p4++)
                ldsm4(bf[p4], su32(&Bs[wn * 64 + p4 * 16 + (lane & 7) + ((lane >> 4) << 3)]
                                      [kk * 16 + ((lane >> 3) & 1) * 8]));
#pragma unroll
            for (int mt = 0; mt < 4; mt++)
#pragma unroll
                for (int nt = 0; nt < 8; nt++)
                    mma16816(acc[mt][nt], af[mt],
                             bf[nt >> 1][(nt & 1) * 2], bf[nt >> 1][(nt & 1) * 2 + 1]);
        }
    }

    const int g = lane >> 2, t = lane & 3;
    float bv[8][2];
#pragma unroll
    for (int nt = 0; nt < 8; nt++) {
        int o = n0 + wn * 64 + nt * 8 + 2 * t;
        bv[nt][0] = bias[o]; bv[nt][1] = bias[o + 1];
    }
#pragma unroll
    for (int mt = 0; mt < 4; mt++) {
        int mA = m0 + wm * 64 + mt * 16 + g;
        int mB = mA + 8;
#pragma unroll
        for (int nt = 0; nt < 8; nt++) {
            int o = n0 + wn * 64 + nt * 8 + 2 * t;
            float v0 = acc[mt][nt][0] + bv[nt][0];
            float v1 = acc[mt][nt][1] + bv[nt][1];
            float v2 = acc[mt][nt][2] + bv[nt][0];
            float v3 = acc[mt][nt][3] + bv[nt][1];
            if (MODE == 0) {
                int which = o >> 10, rem = o & 1023, hh = rem >> 6, d = rem & 63;
                float sc = (which == 0) ? 0.125f : 1.0f;
                __half* dst = (which == 0) ? g_qh : (which == 1) ? g_kh : g_vh;
                int bbA = mA >> 11, nA = mA & (N_ - 1);
                int bbB = mB >> 11, nB = mB & (N_ - 1);
                *(__half2*)&dst[((bbA * H_ + hh) * N_ + nA) * D_ + d] =
                    __floats2half2_rn(v0 * sc, v1 * sc);
                *(__half2*)&dst[((bbB * H_ + hh) * N_ + nB) * D_ + d] =
                    __floats2half2_rn(v2 * sc, v3 * sc);
            } else {
                *(float2*)&out[mA * C_ + o] = make_float2(v0, v1);
                *(float2*)&out[mB * C_ + o] = make_float2(v2, v3);
            }
        }
    }
}

// ---------------- flash attention, HMMA, fp16 in / f32 softmax --------------
// Grid (N/128, B*H). 8 warps; warp w owns Q rows [w*16, w*16+16). KV tile 64.
__global__ __launch_bounds__(256) void attn_h()
{
    __shared__ __half Qs[128][72];
    __shared__ __half Ks[64][72];
    __shared__ __half Vs[64][72];
    const int tid = threadIdx.x, lane = tid & 31, w = tid >> 5;
    const int bh = blockIdx.y, bb = bh >> 4, h = bh & 15;
    const int r0 = blockIdx.x * 128;
    const __half* qp = g_qh + bh * (N_ * D_);
    const __half* kp = g_kh + bh * (N_ * D_);
    const __half* vp = g_vh + bh * (N_ * D_);

    for (int u = tid; u < 1024; u += 256) {
        int r = u >> 3, cc = (u & 7) * 8;
        *(uint4*)&Qs[r][cc] = *(const uint4*)(qp + (r0 + r) * D_ + cc);
    }
    __syncthreads();
    uint32_t qf[4][4];
#pragma unroll
    for (int kk = 0; kk < 4; kk++)
        ldsm4(qf[kk], su32(&Qs[w * 16 + (lane & 15)][kk * 16 + (lane >> 4) * 8]));

    float o_[8][4];
#pragma unroll
    for (int j = 0; j < 8; j++)
#pragma unroll
        for (int r = 0; r < 4; r++) o_[j][r] = 0.f;
    float m0s = -1e30f, m1s = -1e30f, l0 = 0.f, l1 = 0.f;

    for (int c0 = 0; c0 < N_; c0 += 64) {
        __syncthreads();
        for (int u = tid; u < 512; u += 256) {
            int r = u >> 3, cc = (u & 7) * 8;
            *(uint4*)&Ks[r][cc] = *(const uint4*)(kp + (c0 + r) * D_ + cc);
            *(uint4*)&Vs[r][cc] = *(const uint4*)(vp + (c0 + r) * D_ + cc);
        }
        __syncthreads();

        // S = Q K^T  (scale pre-folded into q)
        float s[8][4];
#pragma unroll
        for (int j = 0; j < 8; j++)
#pragma unroll
            for (int r = 0; r < 4; r++) s[j][r] = 0.f;
#pragma unroll
        for (int kk = 0; kk < 4; kk++) {
            uint32_t bf[4][4];
#pragma unroll
            for (int p4 = 0; p4 < 4; p4++)
                ldsm4(bf[p4], su32(&Ks[p4 * 16 + (lane & 7) + ((lane >> 4) << 3)]
                                      [kk * 16 + ((lane >> 3) & 1) * 8]));
#pragma unroll
            for (int j = 0; j < 8; j++)
                mma16816(s[j], qf[kk],
                         bf[j >> 1][(j & 1) * 2], bf[j >> 1][(j & 1) * 2 + 1]);
        }

        // online softmax: rows g (regs 0,1) and g+8 (regs 2,3); 4 lanes per row
        float mx0 = s[0][0], mx1 = s[0][2];
#pragma unroll
        for (int j = 0; j < 8; j++) {
            mx0 = fmaxf(mx0, fmaxf(s[j][0], s[j][1]));
            mx1 = fmaxf(mx1, fmaxf(s[j][2], s[j][3]));
        }
        mx0 = fmaxf(mx0, __shfl_xor_sync(0xffffffffu, mx0, 1));
        mx0 = fmaxf(mx0, __shfl_xor_sync(0xffffffffu, mx0, 2));
        mx1 = fmaxf(mx1, __shfl_xor_sync(0xffffffffu, mx1, 1));
        mx1 = fmaxf(mx1, __shfl_xor_sync(0xffffffffu, mx1, 2));
        float mn0 = fmaxf(m0s, mx0), mn1 = fmaxf(m1s, mx1);
        float a0 = __expf(m0s - mn0), a1 = __expf(m1s - mn1);
        m0s = mn0; m1s = mn1;
        float rs0 = 0.f, rs1 = 0.f;
#pragma unroll
        for (int j = 0; j < 8; j++) {
            s[j][0] = __expf(s[j][0] - mn0);
            s[j][1] = __expf(s[j][1] - mn0);
            s[j][2] = __expf(s[j][2] - mn1);
            s[j][3] = __expf(s[j][3] - mn1);
            rs0 += s[j][0] + s[j][1];
            rs1 += s[j][2] + s[j][3];
            o_[j][0] *= a0; o_[j][1] *= a0;
            o_[j][2] *= a1; o_[j][3] *= a1;
        }
        rs0 += __shfl_xor_sync(0xffffffffu, rs0, 1);
        rs0 += __shfl_xor_sync(0xffffffffu, rs0, 2);
        rs1 += __shfl_xor_sync(0xffffffffu, rs1, 1);
        rs1 += __shfl_xor_sync(0xffffffffu, rs1, 2);
        l0 = l0 * a0 + rs0;
        l1 = l1 * a1 + rs1;

        // O += P V : P repacked in registers (D-frag -> A-frag), V via ldsm.trans
#pragma unroll
        for (int kpi = 0; kpi < 4; kpi++) {
            uint32_t pa[4];
            pa[0] = pk2(s[2 * kpi][1],     s[2 * kpi][0]);
            pa[1] = pk2(s[2 * kpi][3],     s[2 * kpi][2]);
            pa[2] = pk2(s[2 * kpi + 1][1], s[2 * kpi + 1][0]);
            pa[3] = pk2(s[2 * kpi + 1][3], s[2 * kpi + 1][2]);
#pragma unroll
            for (int p4 = 0; p4 < 4; p4++) {
                uint32_t vf[4];
                ldsm4t(vf, su32(&Vs[kpi * 16 + (lane & 7) + (((lane >> 3) & 1) << 3)]
                                   [p4 * 16 + ((lane >> 4) << 3)]));
                mma16816(o_[2 * p4],     pa, vf[0], vf[1]);
                mma16816(o_[2 * p4 + 1], pa, vf[2], vf[3]);
            }
        }
    }

    float i0 = 1.f / l0, i1 = 1.f / l1;
    const int g = lane >> 2, t = lane & 3;
    int nA = r0 + w * 16 + g, nB = nA + 8;
#pragma unroll
    for (int j = 0; j < 8; j++) {
        int col = h * 64 + j * 8 + 2 * t;
        *(__half2*)&g_ah[(bb * N_ + nA) * C_ + col] =
            __floats2half2_rn(o_[j][0] * i0, o_[j][1] * i0);
        *(__half2*)&g_ah[(bb * N_ + nB) * C_ + col] =
            __floats2half2_rn(o_[j][2] * i1, o_[j][3] * i1);
    }
}

// ---------------------------------------------------------------------------

extern "C" void kernel_launch(void* const* d_in, const int* in_sizes, int n_in,
                              void* d_out, int out_size)
{
    const float* x      = (const float*)d_in[0];
    const float* w_qkv  = (const float*)d_in[1];
    const float* b_qkv  = (const float*)d_in[2];
    const float* w_proj = (const float*)d_in[3];
    const float* b_proj = (const float*)d_in[4];
    float* out = (float*)d_out;

    cvt_kernel<0><<<M_*C_ / 1024, 256>>>(x, M_*C_);
    cvt_kernel<1><<<QKV_N*C_ / 1024, 256>>>(w_qkv, QKV_N*C_);
    cvt_kernel<2><<<C_*C_ / 1024, 256>>>(w_proj, C_*C_);

    gemm_h<0><<<dim3(QKV_N / 256, M_ / 128), 256>>>(b_qkv, nullptr);
    attn_h<<<dim3(N_ / 128, B_ * H_), 256>>>();
    gemm_h<1><<<dim3(C_ / 256, M_ / 128), 256>>>(b_proj, out);
}